// round 5
// baseline (speedup 1.0000x reference)
#include <cuda_runtime.h>

// LSTM_21869973471591 — B=4096, T=200, IN=2, H=64 (gates 4H=256)
//
// R5 = R4 mix + 2x occupancy. R2-R4 all plateaued ~900-1000us with
// issue~42%: latency-bound (LDS 29cyc, MUFU 16cyc, barriers) at only
// 4 warps/SMSP. This round: 512-thread CTAs (8 row-groups x 64 units),
// RM=2 rows/thread, NB=16, grid=256, 2 CTAs/SM -> 32 warps/SM =
// 8 warps/SMSP. smem 87KB x 2 = 174KB fits. __launch_bounds__(512,2)
// caps regs at 64 (RM=2 body fits). Same gate-interleaved smem W,
// pre-duplicated {h,h} operands, in-register activation, one barrier/step.

#define B_TOT  4096
#define T_LEN  200
#define H_DIM  64
#define NB     16
#define RM     2            // rows per thread
#define CH     20           // x staging chunk (200 % 20 == 0)
#define NTH    512
#define GRID   (B_TOT / NB) // 256

// dynamic smem layout (bytes)
#define OFF_W   0
#define SZ_W    (64 * 64 * 16)          // Wt4[k][n] = {wi,wf,wg,wo}   65536
#define OFF_HD  (OFF_W + SZ_W)
#define SZ_HD   (2 * NB * 64 * 8)       // hd[2][NB][64] {h,h}         16384
#define OFF_XD  (OFF_HD + SZ_HD)
#define SZ_XD   (NB * CH * 16)          // xd[NB][CH] {x0,x0,x1,x1}     5120
#define SMEM_TOTAL (OFF_XD + SZ_XD)     // 87040 B -> 2 CTAs/SM (174KB)

typedef unsigned long long u64;

__device__ __forceinline__ u64 pack2(float lo, float hi) {
    u64 r; asm("mov.b64 %0, {%1, %2};" : "=l"(r) : "f"(lo), "f"(hi)); return r;
}
__device__ __forceinline__ void unpack2(u64 v, float& lo, float& hi) {
    asm("mov.b64 {%0, %1}, %2;" : "=f"(lo), "=f"(hi) : "l"(v));
}
__device__ __forceinline__ void fma2(u64& acc, u64 a, u64 b) {
    asm("fma.rn.f32x2 %0, %1, %2, %0;" : "+l"(acc) : "l"(a), "l"(b));
}
__device__ __forceinline__ float fast_rcp(float x) {
    float r; asm("rcp.approx.f32 %0, %1;" : "=f"(r) : "f"(x)); return r;
}
__device__ __forceinline__ float fast_ex2(float x) {
    float r; asm("ex2.approx.f32 %0, %1;" : "=f"(r) : "f"(x)); return r;
}
// accurate sigmoid/tanh via ex2.approx (~2^-22) + rcp.approx; validated
// rel_err ~3e-7 across R1-R4.
__device__ __forceinline__ float sigmoid_f(float x) {
    float e = fast_ex2(-1.4426950408889634f * x);
    return fast_rcp(1.0f + e);
}
__device__ __forceinline__ float tanh_f(float x) {
    float e = fast_ex2(2.8853900817779268f * x);
    return fmaf(-2.0f, fast_rcp(1.0f + e), 1.0f);
}

__global__ __launch_bounds__(NTH, 2)
void lstm_kernel(const float* __restrict__ x,      // [B, T, 2]
                 const float* __restrict__ W_ih,   // [256, 2]
                 const float* __restrict__ W_hh,   // [256, 64]
                 const float* __restrict__ b_ih,   // [256]
                 const float* __restrict__ b_hh,   // [256]
                 const float* __restrict__ W_fc,   // [1, 64]
                 const float* __restrict__ b_fc,   // [1]
                 float* __restrict__ out)          // [B, 1]
{
    extern __shared__ char smem[];
    float*            wt_f = (float*)(smem + OFF_W);
    const ulonglong2* wt2  = (const ulonglong2*)(smem + OFF_W);   // [k*64+n] = {wi,wf},{wg,wo}
    u64*              hd   = (u64*)(smem + OFF_HD);               // [(buf*NB+b)*64+k] = {h,h}
    float4*           xd   = (float4*)(smem + OFF_XD);            // [b*CH+tc] = {x0,x0,x1,x1}

    const int tid  = threadIdx.x;
    const int rg   = tid >> 6;          // row-group 0..7
    const int n    = tid & 63;          // hidden unit owned by this thread
    const int row0 = blockIdx.x * NB;

    // per-unit W_ih / bias, packed for fma2
    const u64 wx0_if = pack2(W_ih[(n)*2 + 0],       W_ih[(64 + n)*2 + 0]);
    const u64 wx1_if = pack2(W_ih[(n)*2 + 1],       W_ih[(64 + n)*2 + 1]);
    const u64 wx0_go = pack2(W_ih[(128 + n)*2 + 0], W_ih[(192 + n)*2 + 0]);
    const u64 wx1_go = pack2(W_ih[(128 + n)*2 + 1], W_ih[(192 + n)*2 + 1]);
    const u64 bias_if = pack2(b_ih[n] + b_hh[n],             b_ih[64 + n] + b_hh[64 + n]);
    const u64 bias_go = pack2(b_ih[128 + n] + b_hh[128 + n], b_ih[192 + n] + b_hh[192 + n]);

    // transpose W_hh -> Wt4[k][n] = {Wi,Wf,Wg,Wo}[n][k]; row-groups 0..3 load gate rg
    if (rg < 4) {
        const float4* wrow = (const float4*)(W_hh + (rg * 64 + n) * 64);
        #pragma unroll
        for (int k4 = 0; k4 < 16; k4++) {
            float4 v = wrow[k4];
            wt_f[((4*k4 + 0) * 64 + n) * 4 + rg] = v.x;
            wt_f[((4*k4 + 1) * 64 + n) * 4 + rg] = v.y;
            wt_f[((4*k4 + 2) * 64 + n) * 4 + rg] = v.z;
            wt_f[((4*k4 + 3) * 64 + n) * 4 + rg] = v.w;
        }
    }
    // h = 0 (both buffers)
    for (int i = tid; i < 2 * NB * 64; i += NTH) hd[i] = 0ull;

    float c[RM];
    #pragma unroll
    for (int b = 0; b < RM; b++) c[b] = 0.0f;

    __syncthreads();

    for (int t = 0; t < T_LEN; t++) {
        const int tc = t % CH;
        if (tc == 0) {
            // stage x[t..t+CH) duplicated: {x0,x0,x1,x1}
            for (int idx = tid; idx < NB * CH; idx += NTH) {
                int b = idx / CH, cc = idx - b * CH;
                float2 xv = *(const float2*)(x + ((row0 + b) * T_LEN + t + cc) * 2);
                xd[b * CH + cc] = make_float4(xv.x, xv.x, xv.y, xv.y);
            }
            __syncthreads();
        }

        const int p = t & 1;
        const u64* hrd = hd + (p * NB + rg * RM) * 64;

        // ---- gate phase: packed accumulators {i,f} and {g,o} for 2 rows ----
        u64 aif[RM], ago[RM];
        #pragma unroll
        for (int b = 0; b < RM; b++) {
            ulonglong2 xq = *(const ulonglong2*)&xd[(rg * RM + b) * CH + tc];
            u64 a0 = bias_if; fma2(a0, wx0_if, xq.x); fma2(a0, wx1_if, xq.y);
            u64 a1 = bias_go; fma2(a1, wx0_go, xq.x); fma2(a1, wx1_go, xq.y);
            aif[b] = a0; ago[b] = a1;
        }
        #pragma unroll 8
        for (int m = 0; m < H_DIM / 2; m++) {        // k = 2m, 2m+1
            ulonglong2 w0 = wt2[(2*m)     * 64 + n]; // {wi,wf},{wg,wo} @ k
            ulonglong2 w1 = wt2[(2*m + 1) * 64 + n]; // {wi,wf},{wg,wo} @ k+1
            #pragma unroll
            for (int b = 0; b < RM; b++) {
                ulonglong2 hq = *(const ulonglong2*)&hrd[b * 64 + 2*m]; // {hk,hk},{hk1,hk1}
                fma2(aif[b], w0.x, hq.x);
                fma2(ago[b], w0.y, hq.x);
                fma2(aif[b], w1.x, hq.y);
                fma2(ago[b], w1.y, hq.y);
            }
        }

        // ---- activation, fully in-register; write h for step t+1 ----
        u64* hwr = hd + ((1 - p) * NB + rg * RM) * 64;
        #pragma unroll
        for (int b = 0; b < RM; b++) {
            float gi, gf, gg, go_;
            unpack2(aif[b], gi, gf);
            unpack2(ago[b], gg, go_);
            float iv = sigmoid_f(gi);
            float fv = sigmoid_f(gf);
            float ov = sigmoid_f(go_);
            float gv = tanh_f(gg);
            float cv = fmaf(fv, c[b], iv * gv);
            c[b] = cv;
            float h = ov * tanh_f(cv);
            hwr[b * 64 + n] = pack2(h, h);
        }
        __syncthreads();
    }

    // final h is in buffer 0 (t=199 writes buf 1-(199&1)=0)
    if (tid < NB) {
        float s = b_fc[0];
        const u64* hrow = hd + tid * 64;
        #pragma unroll
        for (int k = 0; k < H_DIM; k++) {
            float lo, hi; unpack2(hrow[k], lo, hi); (void)hi;
            s = fmaf(lo, W_fc[k], s);
        }
        out[row0 + tid] = s;
    }
}

extern "C" void kernel_launch(void* const* d_in, const int* in_sizes, int n_in,
                              void* d_out, int out_size) {
    const float* x    = (const float*)d_in[0];
    const float* W_ih = (const float*)d_in[1];
    const float* W_hh = (const float*)d_in[2];
    const float* b_ih = (const float*)d_in[3];
    const float* b_hh = (const float*)d_in[4];
    const float* W_fc = (const float*)d_in[5];
    const float* b_fc = (const float*)d_in[6];
    float* out = (float*)d_out;
    (void)in_sizes; (void)n_in; (void)out_size;

    static int attr_set = 0;
    if (!attr_set) {
        cudaFuncSetAttribute(lstm_kernel,
                             cudaFuncAttributeMaxDynamicSharedMemorySize,
                             SMEM_TOTAL);
        attr_set = 1;
    }
    lstm_kernel<<<GRID, NTH, SMEM_TOTAL>>>(x, W_ih, W_hh, b_ih, b_hh,
                                           W_fc, b_fc, out);
}

// round 7
// speedup vs baseline: 1.3781x; 1.3781x over previous
#include <cuda_runtime.h>

// LSTM_21869973471591 — B=4096, T=200, IN=2, H=64 (gates 4H=256)
//
// R7 = R6 design, compile-fixed (static smem was >48KB). Partials are now
// pre-summed to a single float per (kh, row, gate-row): g_p float[2*NB][256]
// = 28KB; total static smem 34.5KB.
//  - thread (j = tid&255, kh = tid>>8) owns gate row j over k in
//    [kh*32, kh*32+32): W = 16 u64 = 32 regs.
//  - 512-thread CTAs, NB=14, grid=293, __launch_bounds__(512,2):
//    <=64 regs -> 2 CTAs/SM = 32 warps/SM = 8 warps/SMSP.
//  - h plain fp32 in smem, single-buffered; h loads are ulonglong2
//    (4 k's / 16B), WARP-BROADCAST (lanes differ only in j) -> ~zero
//    crossbar cost (coalesced W streaming killed R5).
//  - act phase (448 threads) adds the two kh partials per gate, applies
//    sigmoid/tanh, c in registers; group-A/B pipeline, 2 barriers/step.

#define B_TOT  4096
#define T_LEN  200
#define H_DIM  64
#define NB     14
#define NBH    7
#define CH     20              // x staging chunk (200 % 20 == 0)
#define NTH    512
#define GRID   ((B_TOT + NB - 1) / NB)   // 293

typedef unsigned long long u64;

__device__ __forceinline__ u64 pack2(float lo, float hi) {
    u64 r; asm("mov.b64 %0, {%1, %2};" : "=l"(r) : "f"(lo), "f"(hi)); return r;
}
__device__ __forceinline__ void unpack2(u64 v, float& lo, float& hi) {
    asm("mov.b64 {%0, %1}, %2;" : "=f"(lo), "=f"(hi) : "l"(v));
}
__device__ __forceinline__ void fma2(u64& acc, u64 a, u64 b) {
    asm("fma.rn.f32x2 %0, %1, %2, %0;" : "+l"(acc) : "l"(a), "l"(b));
}
__device__ __forceinline__ float fast_rcp(float x) {
    float r; asm("rcp.approx.f32 %0, %1;" : "=f"(r) : "f"(x)); return r;
}
__device__ __forceinline__ float fast_ex2(float x) {
    float r; asm("ex2.approx.f32 %0, %1;" : "=f"(r) : "f"(x)); return r;
}
// accurate sigmoid/tanh via ex2.approx + rcp.approx (rel_err ~3e-7 R1-R5)
__device__ __forceinline__ float sigmoid_f(float x) {
    float e = fast_ex2(-1.4426950408889634f * x);
    return fast_rcp(1.0f + e);
}
__device__ __forceinline__ float tanh_f(float x) {
    float e = fast_ex2(2.8853900817779268f * x);
    return fmaf(-2.0f, fast_rcp(1.0f + e), 1.0f);
}

__global__ __launch_bounds__(NTH, 2)
void lstm_kernel(const float* __restrict__ x,      // [B, T, 2]
                 const float* __restrict__ W_ih,   // [256, 2]
                 const float* __restrict__ W_hh,   // [256, 64]
                 const float* __restrict__ b_ih,   // [256]
                 const float* __restrict__ b_hh,   // [256]
                 const float* __restrict__ W_fc,   // [1, 64]
                 const float* __restrict__ b_fc,   // [1]
                 float* __restrict__ out)          // [B, 1]
{
    // static smem: 3584 + 28672 + 2240 = 34496 B (< 48KB static cap)
    __shared__ __align__(16) float h_s[NB][H_DIM];     // plain fp32, single buffer
    __shared__ __align__(16) float g_p[2 * NB][256];   // [kh*NB+b][j] partial sums
    __shared__ __align__(16) float x_s[NB][CH][2];

    const int tid  = threadIdx.x;
    const int j    = tid & 255;          // gate row
    const int kh   = tid >> 8;           // k-half 0/1
    const int kb   = kh * 32;            // k base
    const int row0 = blockIdx.x * NB;

    // W_hh[j][kb .. kb+32) as 16 u64 pairs
    u64 w2[16];
    {
        const float4* wrow = (const float4*)(W_hh + j * H_DIM + kb);
        #pragma unroll
        for (int m = 0; m < 8; m++) {
            float4 v = wrow[m];
            w2[2*m + 0] = pack2(v.x, v.y);
            w2[2*m + 1] = pack2(v.z, v.w);
        }
    }
    // x-path constants (only kh=0 injects x+bias)
    const float wi0  = (kh == 0) ? W_ih[j * 2 + 0] : 0.0f;
    const float wi1  = (kh == 0) ? W_ih[j * 2 + 1] : 0.0f;
    const float bias = (kh == 0) ? (b_ih[j] + b_hh[j]) : 0.0f;

    // h0 = 0
    for (int i = tid; i < NB * H_DIM; i += NTH)
        (&h_s[0][0])[i] = 0.0f;
    float cA = 0.0f, cB = 0.0f;          // c-state for act threads (tid<448)
    __syncthreads();

    // gate phase for rows [b0, b0+7): pre-summed float partials
    auto gate_phase = [&](int b0, int tc) {
        u64 acc[NBH];
        #pragma unroll
        for (int b = 0; b < NBH; b++) {
            float2 xv = *(const float2*)&x_s[b0 + b][tc][0];
            float xg = fmaf(xv.y, wi1, fmaf(xv.x, wi0, bias));  // 0 for kh=1
            acc[b] = pack2(xg, 0.0f);
        }
        #pragma unroll
        for (int m = 0; m < 8; m++) {
            #pragma unroll
            for (int b = 0; b < NBH; b++) {
                // 16B broadcast: 4 k's of row b (lanes differ only in j)
                ulonglong2 hq = *(const ulonglong2*)&h_s[b0 + b][kb + 4*m];
                fma2(acc[b], w2[2*m + 0], hq.x);
                fma2(acc[b], w2[2*m + 1], hq.y);
            }
        }
        #pragma unroll
        for (int b = 0; b < NBH; b++) {
            float ev, od; unpack2(acc[b], ev, od);
            g_p[kh * NB + b0 + b][j] = ev + od;
        }
    };

    // act phase for rows [b0, b0+7): 448 threads, elem = (b, n)
    auto act_phase = [&](int b0, float& c) {
        if (tid < NBH * H_DIM) {
            int b = b0 + (tid >> 6);
            int n = tid & 63;
            float gi  = g_p[b][n]       + g_p[NB + b][n];
            float gf  = g_p[b][64 + n]  + g_p[NB + b][64 + n];
            float gg  = g_p[b][128 + n] + g_p[NB + b][128 + n];
            float go_ = g_p[b][192 + n] + g_p[NB + b][192 + n];
            float iv = sigmoid_f(gi);
            float fv = sigmoid_f(gf);
            float ov = sigmoid_f(go_);
            float gv = tanh_f(gg);
            float cv = fmaf(fv, c, iv * gv);
            c = cv;
            h_s[b][n] = ov * tanh_f(cv);
        }
    };

    for (int t = 0; t < T_LEN; t++) {
        const int tc = t % CH;
        if (tc == 0) {
            // stage x[t..t+CH) (rows clamped for the 8-row tail CTA)
            for (int idx = tid; idx < NB * CH; idx += NTH) {
                int b = idx / CH, cc = idx - b * CH;
                int row = row0 + b; if (row > B_TOT - 1) row = B_TOT - 1;
                *(float2*)&x_s[b][cc][0] =
                    *(const float2*)(x + (row * T_LEN + t + cc) * 2);
            }
            __syncthreads();
        }
        // phase 1: gates(A=rows 0..6, t) ; act(B=rows 7..13, gates of t-1)
        gate_phase(0, tc);
        if (t > 0) act_phase(NBH, cB);
        __syncthreads();
        // phase 2: gates(B, t) [h rows 7..13 fresh] ; act(A, gates of t)
        gate_phase(NBH, tc);
        act_phase(0, cA);
        __syncthreads();
    }
    // drain act(B, t=199)
    act_phase(NBH, cB);
    __syncthreads();

    // fc head
    if (tid < NB) {
        int row = row0 + tid;
        if (row < B_TOT) {
            float s = b_fc[0];
            #pragma unroll
            for (int k = 0; k < H_DIM; k++)
                s = fmaf(h_s[tid][k], W_fc[k], s);
            out[row] = s;
        }
    }
}

extern "C" void kernel_launch(void* const* d_in, const int* in_sizes, int n_in,
                              void* d_out, int out_size) {
    const float* x    = (const float*)d_in[0];
    const float* W_ih = (const float*)d_in[1];
    const float* W_hh = (const float*)d_in[2];
    const float* b_ih = (const float*)d_in[3];
    const float* b_hh = (const float*)d_in[4];
    const float* W_fc = (const float*)d_in[5];
    const float* b_fc = (const float*)d_in[6];
    float* out = (float*)d_out;
    (void)in_sizes; (void)n_in; (void)out_size;

    lstm_kernel<<<GRID, NTH>>>(x, W_ih, W_hh, b_ih, b_hh, W_fc, b_fc, out);
}

// round 8
// speedup vs baseline: 1.5251x; 1.1066x over previous
#include <cuda_runtime.h>

// LSTM_21869973471591 — B=4096, T=200, IN=2, H=64 (gates 4H=256)
//
// R8: 8 MACs per LDS.128 (vs 4 in all prior rounds). The R2-R7 plateau was
// the shared/RF-write pipe: a broadcast LDS.128 still writes 512B to the RF
// (~4cyc), and at 1 load : 2 fma2 the LDS pipe matched the fma pipe. Now
// each thread owns TWO gate rows (pr, pr+128) over a 16-wide k-span, so one
// h quad {hk..hk+3} feeds 4 fma2 -> LDS per step halves.
//  - thread (pr = tid&127, ks = tid>>7): W = 2x16 fp32 = 16 u64 = 32 regs.
//  - per-b local accumulators (u64 {even,odd}) keep regs <= 64 ->
//    512-thread CTAs, 2 CTAs/SM = 32 warps/SM (NB=14, grid=293).
//  - 4-way k-split partials g_p[4*NB][256] = 57KB -> DYNAMIC smem (63KB/CTA).
//  - act phase (448 threads) sums 4 partials/gate, sigmoid/tanh, c in regs;
//    A/B group software pipeline, 2 barriers/step.

#define B_TOT  4096
#define T_LEN  200
#define H_DIM  64
#define NB     14
#define NBH    7
#define CH     20              // x staging chunk (200 % 20 == 0)
#define NTH    512
#define GRID   ((B_TOT + NB - 1) / NB)   // 293

// dynamic smem layout (floats)
#define OFF_GP  0
#define SZ_GP   (4 * NB * 256)           // 57344 B
#define OFF_H   (OFF_GP + SZ_GP)
#define SZ_H    (NB * H_DIM)             // 3584 B
#define OFF_X   (OFF_H + SZ_H)
#define SZ_X    (NB * CH * 2)            // 2240 B
#define SMEM_FLOATS (OFF_X + SZ_X)
#define SMEM_BYTES  (SMEM_FLOATS * 4)    // 63168 B -> 2 CTAs/SM

typedef unsigned long long u64;

__device__ __forceinline__ u64 pack2(float lo, float hi) {
    u64 r; asm("mov.b64 %0, {%1, %2};" : "=l"(r) : "f"(lo), "f"(hi)); return r;
}
__device__ __forceinline__ void unpack2(u64 v, float& lo, float& hi) {
    asm("mov.b64 {%0, %1}, %2;" : "=f"(lo), "=f"(hi) : "l"(v));
}
__device__ __forceinline__ void fma2(u64& acc, u64 a, u64 b) {
    asm("fma.rn.f32x2 %0, %1, %2, %0;" : "+l"(acc) : "l"(a), "l"(b));
}
__device__ __forceinline__ float fast_rcp(float x) {
    float r; asm("rcp.approx.f32 %0, %1;" : "=f"(r) : "f"(x)); return r;
}
__device__ __forceinline__ float fast_ex2(float x) {
    float r; asm("ex2.approx.f32 %0, %1;" : "=f"(r) : "f"(x)); return r;
}
// accurate sigmoid/tanh via ex2.approx + rcp.approx (rel_err ~3e-7 R1-R7)
__device__ __forceinline__ float sigmoid_f(float x) {
    float e = fast_ex2(-1.4426950408889634f * x);
    return fast_rcp(1.0f + e);
}
__device__ __forceinline__ float tanh_f(float x) {
    float e = fast_ex2(2.8853900817779268f * x);
    return fmaf(-2.0f, fast_rcp(1.0f + e), 1.0f);
}

__global__ __launch_bounds__(NTH, 2)
void lstm_kernel(const float* __restrict__ x,      // [B, T, 2]
                 const float* __restrict__ W_ih,   // [256, 2]
                 const float* __restrict__ W_hh,   // [256, 64]
                 const float* __restrict__ b_ih,   // [256]
                 const float* __restrict__ b_hh,   // [256]
                 const float* __restrict__ W_fc,   // [1, 64]
                 const float* __restrict__ b_fc,   // [1]
                 float* __restrict__ out)          // [B, 1]
{
    extern __shared__ float sm[];
    float* g_p = sm + OFF_GP;            // [ (ks*NB + b)*256 + j ]
    float* h_s = sm + OFF_H;             // [ b*64 + k ]
    float* x_s = sm + OFF_X;             // [ (b*CH + tc)*2 ]

    const int tid  = threadIdx.x;
    const int pr   = tid & 127;          // gate-row pair index
    const int ks   = tid >> 7;           // k-span 0..3
    const int kb   = ks * 16;            // k base
    const int j0   = pr;                 // gate row A (i/f region)
    const int j1   = pr + 128;           // gate row B (g/o region)
    const int row0 = blockIdx.x * NB;

    // W_hh rows j0, j1 over [kb, kb+16) as 8+8 u64 pairs
    u64 w0[8], w1[8];
    {
        const float4* wr0 = (const float4*)(W_hh + j0 * H_DIM + kb);
        const float4* wr1 = (const float4*)(W_hh + j1 * H_DIM + kb);
        #pragma unroll
        for (int m = 0; m < 4; m++) {
            float4 a = wr0[m], b = wr1[m];
            w0[2*m + 0] = pack2(a.x, a.y);  w0[2*m + 1] = pack2(a.z, a.w);
            w1[2*m + 0] = pack2(b.x, b.y);  w1[2*m + 1] = pack2(b.z, b.w);
        }
    }
    // x-path constants (only ks==0 injects x+bias)
    const bool  inj   = (ks == 0);
    const float wiA0  = inj ? W_ih[j0 * 2 + 0] : 0.0f;
    const float wiA1  = inj ? W_ih[j0 * 2 + 1] : 0.0f;
    const float biasA = inj ? (b_ih[j0] + b_hh[j0]) : 0.0f;
    const float wiB0  = inj ? W_ih[j1 * 2 + 0] : 0.0f;
    const float wiB1  = inj ? W_ih[j1 * 2 + 1] : 0.0f;
    const float biasB = inj ? (b_ih[j1] + b_hh[j1]) : 0.0f;

    // h0 = 0
    for (int i = tid; i < NB * H_DIM; i += NTH) h_s[i] = 0.0f;
    float cA = 0.0f, cB = 0.0f;          // c-state for act threads (tid<448)
    __syncthreads();

    // gate phase for rows [b0, b0+7): per-b local accumulators
    auto gate_phase = [&](int b0, int tc) {
        #pragma unroll
        for (int b = 0; b < NBH; b++) {
            const int br = b0 + b;
            float2 xv = *(const float2*)&x_s[(br * CH + tc) * 2];
            float xgA = fmaf(xv.y, wiA1, fmaf(xv.x, wiA0, biasA));  // 0 if !inj
            float xgB = fmaf(xv.y, wiB1, fmaf(xv.x, wiB0, biasB));
            u64 acc0 = pack2(xgA, 0.0f);
            u64 acc1 = pack2(xgB, 0.0f);
            const ulonglong2* hb = (const ulonglong2*)(h_s + br * H_DIM + kb);
            #pragma unroll
            for (int m = 0; m < 4; m++) {
                ulonglong2 hq = hb[m];        // {hk,hk+1},{hk+2,hk+3} broadcast
                fma2(acc0, w0[2*m + 0], hq.x);
                fma2(acc0, w0[2*m + 1], hq.y);
                fma2(acc1, w1[2*m + 0], hq.x);
                fma2(acc1, w1[2*m + 1], hq.y);
            }
            float ev, od;
            unpack2(acc0, ev, od); g_p[(ks * NB + br) * 256 + j0] = ev + od;
            unpack2(acc1, ev, od); g_p[(ks * NB + br) * 256 + j1] = ev + od;
        }
    };

    // act phase for rows [b0, b0+7): 448 threads, elem = (b, n)
    auto act_phase = [&](int b0, float& c) {
        if (tid < NBH * H_DIM) {
            int b = b0 + (tid >> 6);
            int n = tid & 63;
            const float* gp0 = g_p + (0 * NB + b) * 256;
            const float* gp1 = g_p + (1 * NB + b) * 256;
            const float* gp2 = g_p + (2 * NB + b) * 256;
            const float* gp3 = g_p + (3 * NB + b) * 256;
            float gi  = (gp0[n]       + gp1[n])       + (gp2[n]       + gp3[n]);
            float gf  = (gp0[64 + n]  + gp1[64 + n])  + (gp2[64 + n]  + gp3[64 + n]);
            float gg  = (gp0[128 + n] + gp1[128 + n]) + (gp2[128 + n] + gp3[128 + n]);
            float go_ = (gp0[192 + n] + gp1[192 + n]) + (gp2[192 + n] + gp3[192 + n]);
            float iv = sigmoid_f(gi);
            float fv = sigmoid_f(gf);
            float ov = sigmoid_f(go_);
            float gv = tanh_f(gg);
            float cv = fmaf(fv, c, iv * gv);
            c = cv;
            h_s[b * H_DIM + n] = ov * tanh_f(cv);
        }
    };

    for (int t = 0; t < T_LEN; t++) {
        const int tc = t % CH;
        if (tc == 0) {
            // stage x[t..t+CH) (rows clamped for the tail CTA)
            for (int idx = tid; idx < NB * CH; idx += NTH) {
                int b = idx / CH, cc = idx - b * CH;
                int row = row0 + b; if (row > B_TOT - 1) row = B_TOT - 1;
                *(float2*)&x_s[(b * CH + cc) * 2] =
                    *(const float2*)(x + (row * T_LEN + t + cc) * 2);
            }
            __syncthreads();
        }
        // phase 1: gates(A=rows 0..6, t) ; act(B=rows 7..13, gates of t-1)
        gate_phase(0, tc);
        if (t > 0) act_phase(NBH, cB);
        __syncthreads();
        // phase 2: gates(B, t) [h rows 7..13 fresh] ; act(A, gates of t)
        gate_phase(NBH, tc);
        act_phase(0, cA);
        __syncthreads();
    }
    // drain act(B, t=199)
    act_phase(NBH, cB);
    __syncthreads();

    // fc head
    if (tid < NB) {
        int row = row0 + tid;
        if (row < B_TOT) {
            float s = b_fc[0];
            #pragma unroll
            for (int k = 0; k < H_DIM; k++)
                s = fmaf(h_s[tid * H_DIM + k], W_fc[k], s);
            out[row] = s;
        }
    }
}

extern "C" void kernel_launch(void* const* d_in, const int* in_sizes, int n_in,
                              void* d_out, int out_size) {
    const float* x    = (const float*)d_in[0];
    const float* W_ih = (const float*)d_in[1];
    const float* W_hh = (const float*)d_in[2];
    const float* b_ih = (const float*)d_in[3];
    const float* b_hh = (const float*)d_in[4];
    const float* W_fc = (const float*)d_in[5];
    const float* b_fc = (const float*)d_in[6];
    float* out = (float*)d_out;
    (void)in_sizes; (void)n_in; (void)out_size;

    static int attr_set = 0;
    if (!attr_set) {
        cudaFuncSetAttribute(lstm_kernel,
                             cudaFuncAttributeMaxDynamicSharedMemorySize,
                             SMEM_BYTES);
        attr_set = 1;
    }
    lstm_kernel<<<GRID, NTH, SMEM_BYTES>>>(x, W_ih, W_hh, b_ih, b_hh,
                                           W_fc, b_fc, out);
}

// round 10
// speedup vs baseline: 2.9971x; 1.9652x over previous
#include <cuda_runtime.h>
#include <cuda_fp16.h>
#include <cstdint>

// LSTM_21869973471591 — B=4096, T=200, IN=2, H=64 (gates 4H=256)
//
// R10: warp-level tensor cores via baseline mma.sync (sm_80+ PTX — compiles
// for the harness's plain sm_100 target; tcgen05 needs sm_100a and is
// unavailable). Per CTA: D[256 gates, 32 rows] = W_hh @ h^T per step.
//  - grid 128 x 32 rows, 512 threads (16 warps); warp w owns gate rows
//    [16w, 16w+16): D[16,32] via m16n8k16 f32.f16.f16.f32.
//  - W fragments REGISTER-RESIDENT for all 200 steps (whi/wlo, 32 regs).
//  - fp32 fidelity: f16 3-term split Whi*hhi + Wlo*hhi + Whi*hlo
//    (f16 mantissa 11b -> product err ~2^-21), fp32 accumulation.
//  - h in smem as f16 hi/lo [32][72] (bank-spread); B frags = 2 LDS.32.
//  - D drains to gs2[b][j] (pad 264, conflict-free), one act pass
//    (MUFU sigmoid/tanh, c in regs), h re-split to f16. 2 barriers/step.

#define B_TOT 4096
#define T_LEN 200
#define NROW  32
#define NTH   512
#define GRID  (B_TOT / NROW)   // 128
#define CH    20               // x staging chunk (200 % 20 == 0)

#define GS_PAD 264             // floats per gs2 row (264 mod 32 = 8)
#define HB_PAD 72              // halfs per h row (144 B -> bank-spread)

__device__ __forceinline__ void mma_f16(float d[4], const uint32_t a[4],
                                        uint32_t b0, uint32_t b1) {
    asm volatile(
        "mma.sync.aligned.m16n8k16.row.col.f32.f16.f16.f32 "
        "{%0,%1,%2,%3}, {%4,%5,%6,%7}, {%8,%9}, {%0,%1,%2,%3};"
        : "+f"(d[0]), "+f"(d[1]), "+f"(d[2]), "+f"(d[3])
        : "r"(a[0]), "r"(a[1]), "r"(a[2]), "r"(a[3]), "r"(b0), "r"(b1));
}

__device__ __forceinline__ uint16_t h_bits(__half h) {
    return *reinterpret_cast<uint16_t*>(&h);
}
// split two fp32 into packed f16 {hi-part pair, lo-part pair}; lane order:
// low 16 bits = first (even-k) element, matching mma fragment packing.
__device__ __forceinline__ void split_pack(float a, float b,
                                           uint32_t& hip, uint32_t& lop) {
    __half ah = __float2half_rn(a), bh = __float2half_rn(b);
    __half al = __float2half_rn(a - __half2float(ah));
    __half bl = __float2half_rn(b - __half2float(bh));
    hip = ((uint32_t)h_bits(bh) << 16) | h_bits(ah);
    lop = ((uint32_t)h_bits(bl) << 16) | h_bits(al);
}

__device__ __forceinline__ float fast_rcp(float x) {
    float r; asm("rcp.approx.f32 %0, %1;" : "=f"(r) : "f"(x)); return r;
}
__device__ __forceinline__ float fast_ex2(float x) {
    float r; asm("ex2.approx.f32 %0, %1;" : "=f"(r) : "f"(x)); return r;
}
__device__ __forceinline__ float sigmoid_f(float x) {
    float e = fast_ex2(-1.4426950408889634f * x);
    return fast_rcp(1.0f + e);
}
__device__ __forceinline__ float tanh_f(float x) {
    float e = fast_ex2(2.8853900817779268f * x);
    return fmaf(-2.0f, fast_rcp(1.0f + e), 1.0f);
}

__global__ __launch_bounds__(NTH)
void lstm_mma(const float* __restrict__ x,      // [B, T, 2]
              const float* __restrict__ W_ih,   // [256, 2]
              const float* __restrict__ W_hh,   // [256, 64]
              const float* __restrict__ b_ih,   // [256]
              const float* __restrict__ b_hh,   // [256]
              const float* __restrict__ W_fc,   // [1, 64]
              const float* __restrict__ b_fc,   // [1]
              float* __restrict__ out)          // [B, 1]
{
    __shared__ float  gs2[NROW][GS_PAD];        // gates [b][j]   33792 B
    __shared__ __half hbhi[NROW][HB_PAD];       // h hi  [b][k]    4608 B
    __shared__ __half hblo[NROW][HB_PAD];       // h lo  [b][k]    4608 B
    __shared__ float2 xs[NROW][CH];             //                 5120 B

    const int tid  = threadIdx.x;
    const int warp = tid >> 5;
    const int lane = tid & 31;
    const int g    = lane >> 2;                 // fragment group row
    const int tg   = lane & 3;                  // thread-in-group
    const int jb   = warp * 16;                 // this warp's gate-row base
    const int row0 = blockIdx.x * NROW;

    // ---- build W fragments (once, register-resident): [kt][a0..a3] ----
    uint32_t whi[4][4], wlo[4][4];
    {
        const float* r0 = W_hh + (jb + g) * 64;
        const float* r1 = W_hh + (jb + 8 + g) * 64;
        #pragma unroll
        for (int kt = 0; kt < 4; kt++) {
            const int k0 = kt * 16 + 2 * tg;
            split_pack(r0[k0],     r0[k0 + 1], whi[kt][0], wlo[kt][0]);
            split_pack(r1[k0],     r1[k0 + 1], whi[kt][1], wlo[kt][1]);
            split_pack(r0[k0 + 8], r0[k0 + 9], whi[kt][2], wlo[kt][2]);
            split_pack(r1[k0 + 8], r1[k0 + 9], whi[kt][3], wlo[kt][3]);
        }
    }

    // ---- act identities: thread owns hidden unit n for 4 batch cols ----
    const int n   = tid & 63;
    const int col = tid >> 6;                   // 0..7
    float wiA[4], wiB[4], bia[4];
    #pragma unroll
    for (int q = 0; q < 4; q++) {
        int j = q * 64 + n;
        wiA[q] = W_ih[j * 2 + 0];
        wiB[q] = W_ih[j * 2 + 1];
        bia[q] = b_ih[j] + b_hh[j];
    }
    float c[4]  = {0.f, 0.f, 0.f, 0.f};
    float hl4[4] = {0.f, 0.f, 0.f, 0.f};

    // h0 = 0 (both split arrays)
    for (int i = tid; i < NROW * HB_PAD / 2; i += NTH) {
        ((uint32_t*)hbhi)[i] = 0u;
        ((uint32_t*)hblo)[i] = 0u;
    }

    for (int t = 0; t < T_LEN; t++) {
        const int tc = t % CH;
        __syncthreads();                        // (1) h writes / gs2 reads done
        if (tc == 0) {
            for (int idx = tid; idx < NROW * CH; idx += NTH) {
                int b = idx / CH, cc = idx - b * CH;
                xs[b][cc] = *(const float2*)(x + ((row0 + b) * T_LEN + t + cc) * 2);
            }
        }

        // ---- MMA phase: D[16, 32] for this warp, 3 split terms ----
        float d[4][4];
        #pragma unroll
        for (int nt = 0; nt < 4; nt++) {
            const int b = nt * 8 + g;
            const __half* hh = hbhi[b];
            const __half* hl = hblo[b];
            uint32_t bh[4][2], bl[4][2];
            #pragma unroll
            for (int kt = 0; kt < 4; kt++) {
                const int k0 = kt * 16 + 2 * tg;
                bh[kt][0] = *(const uint32_t*)(hh + k0);
                bh[kt][1] = *(const uint32_t*)(hh + k0 + 8);
                bl[kt][0] = *(const uint32_t*)(hl + k0);
                bl[kt][1] = *(const uint32_t*)(hl + k0 + 8);
            }
            #pragma unroll
            for (int r = 0; r < 4; r++) d[nt][r] = 0.0f;
            #pragma unroll
            for (int kt = 0; kt < 4; kt++)
                mma_f16(d[nt], whi[kt], bh[kt][0], bh[kt][1]);
            #pragma unroll
            for (int kt = 0; kt < 4; kt++)
                mma_f16(d[nt], wlo[kt], bh[kt][0], bh[kt][1]);
            #pragma unroll
            for (int kt = 0; kt < 4; kt++)
                mma_f16(d[nt], whi[kt], bl[kt][0], bl[kt][1]);
        }
        // drain D -> gs2[b][j]
        #pragma unroll
        for (int nt = 0; nt < 4; nt++) {
            const int br = nt * 8 + 2 * tg;
            gs2[br][jb + g]         = d[nt][0];
            gs2[br + 1][jb + g]     = d[nt][1];
            gs2[br][jb + 8 + g]     = d[nt][2];
            gs2[br + 1][jb + 8 + g] = d[nt][3];
        }
        __syncthreads();                        // (2) gates + xs visible

        // ---- activation: 4 (b, n) elements per thread ----
        #pragma unroll
        for (int i = 0; i < 4; i++) {
            const int b = col + 8 * i;
            float2 xv = xs[b][tc];
            float gi  = gs2[b][n]        + fmaf(xv.y, wiB[0], fmaf(xv.x, wiA[0], bia[0]));
            float gf  = gs2[b][64 + n]   + fmaf(xv.y, wiB[1], fmaf(xv.x, wiA[1], bia[1]));
            float gg  = gs2[b][128 + n]  + fmaf(xv.y, wiB[2], fmaf(xv.x, wiA[2], bia[2]));
            float go_ = gs2[b][192 + n]  + fmaf(xv.y, wiB[3], fmaf(xv.x, wiA[3], bia[3]));
            float iv = sigmoid_f(gi);
            float fv = sigmoid_f(gf);
            float ov = sigmoid_f(go_);
            float gv = tanh_f(gg);
            float cv = fmaf(fv, c[i], iv * gv);
            c[i] = cv;
            float h = ov * tanh_f(cv);
            hl4[i] = h;
            __half hh = __float2half_rn(h);
            hbhi[b][n] = hh;
            hblo[b][n] = __float2half_rn(h - __half2float(hh));
        }
    }

    // ---- fc head: stage final h (fp32) into gs2, reduce ----
    __syncthreads();
    #pragma unroll
    for (int i = 0; i < 4; i++)
        gs2[col + 8 * i][n] = hl4[i];
    __syncthreads();
    if (tid < NROW) {
        float s = b_fc[0];
        #pragma unroll
        for (int k = 0; k < 64; k++)
            s = fmaf(gs2[tid][k], W_fc[k], s);
        out[row0 + tid] = s;
    }
}

extern "C" void kernel_launch(void* const* d_in, const int* in_sizes, int n_in,
                              void* d_out, int out_size) {
    const float* x    = (const float*)d_in[0];
    const float* W_ih = (const float*)d_in[1];
    const float* W_hh = (const float*)d_in[2];
    const float* b_ih = (const float*)d_in[3];
    const float* b_hh = (const float*)d_in[4];
    const float* W_fc = (const float*)d_in[5];
    const float* b_fc = (const float*)d_in[6];
    float* out = (float*)d_out;
    (void)in_sizes; (void)n_in; (void)out_size;

    lstm_mma<<<GRID, NTH>>>(x, W_ih, W_hh, b_ih, b_hh, W_fc, b_fc, out);
}

// round 11
// speedup vs baseline: 3.3670x; 1.1234x over previous
#include <cuda_runtime.h>
#include <cuda_fp16.h>
#include <cstdint>

// LSTM_21869973471591 — B=4096, T=200, IN=2, H=64 (gates 4H=256)
//
// R11 = R10 (warp-level mma.sync f16 split) + two cuts:
//  (1) 2-term split: Whi*hhi + Whi*hlo (drops the static W-correction term;
//      W is f16-rounded -> static 2.4e-4 relative perturbation, expected
//      final rel_err ~1e-4 << 1e-3). -33% tensor work, -16 W regs.
//  (2) A/B batch-group software pipeline: rows 0-15 / 16-31.
//      phase1: MMA_A(t) || act_B(t-1);  phase2: MMA_B(t) || act_A(t).
//      MUFU activation hides under dependent-MMA latency. 2 barriers/step.
//  x double-buffered (CH=10) so act(t-1) never reads a restaged chunk.
//  gs2 pad 260 (== 4 mod 16) -> conflict-free drain stores; smem 47.6KB.

#define B_TOT 4096
#define T_LEN 200
#define NROW  32
#define NTH   512
#define GRID  (B_TOT / NROW)   // 128
#define CH    10               // x staging chunk (200 % 10 == 0)

#define GS_PAD 260             // floats per gs2 row; 260 % 16 == 4 -> drain conflict-free
#define HB_PAD 72              // halfs per h row (144 B, frag loads conflict-free)

__device__ __forceinline__ void mma_f16(float d[4], const uint32_t a[4],
                                        uint32_t b0, uint32_t b1) {
    asm volatile(
        "mma.sync.aligned.m16n8k16.row.col.f32.f16.f16.f32 "
        "{%0,%1,%2,%3}, {%4,%5,%6,%7}, {%8,%9}, {%0,%1,%2,%3};"
        : "+f"(d[0]), "+f"(d[1]), "+f"(d[2]), "+f"(d[3])
        : "r"(a[0]), "r"(a[1]), "r"(a[2]), "r"(a[3]), "r"(b0), "r"(b1));
}

__device__ __forceinline__ uint16_t h_bits(__half h) {
    return *reinterpret_cast<uint16_t*>(&h);
}
__device__ __forceinline__ uint32_t pack_h2(float a, float b) {
    __half ah = __float2half_rn(a), bh = __float2half_rn(b);
    return ((uint32_t)h_bits(bh) << 16) | h_bits(ah);
}

__device__ __forceinline__ float fast_rcp(float x) {
    float r; asm("rcp.approx.f32 %0, %1;" : "=f"(r) : "f"(x)); return r;
}
__device__ __forceinline__ float fast_ex2(float x) {
    float r; asm("ex2.approx.f32 %0, %1;" : "=f"(r) : "f"(x)); return r;
}
__device__ __forceinline__ float sigmoid_f(float x) {
    float e = fast_ex2(-1.4426950408889634f * x);
    return fast_rcp(1.0f + e);
}
__device__ __forceinline__ float tanh_f(float x) {
    float e = fast_ex2(2.8853900817779268f * x);
    return fmaf(-2.0f, fast_rcp(1.0f + e), 1.0f);
}

__global__ __launch_bounds__(NTH)
void lstm_mma(const float* __restrict__ x,      // [B, T, 2]
              const float* __restrict__ W_ih,   // [256, 2]
              const float* __restrict__ W_hh,   // [256, 64]
              const float* __restrict__ b_ih,   // [256]
              const float* __restrict__ b_hh,   // [256]
              const float* __restrict__ W_fc,   // [1, 64]
              const float* __restrict__ b_fc,   // [1]
              float* __restrict__ out)          // [B, 1]
{
    __shared__ float  gs2[NROW][GS_PAD];        // gates [b][j]    33280 B
    __shared__ __half hbhi[NROW][HB_PAD];       // h hi  [b][k]     4608 B
    __shared__ __half hblo[NROW][HB_PAD];       // h lo  [b][k]     4608 B
    __shared__ float2 xs[2][NROW][CH];          // double-buffered  5120 B

    const int tid  = threadIdx.x;
    const int warp = tid >> 5;
    const int lane = tid & 31;
    const int g    = lane >> 2;                 // fragment group row
    const int tg   = lane & 3;                  // thread-in-group
    const int jb   = warp * 16;                 // this warp's gate-row base
    const int row0 = blockIdx.x * NROW;

    // ---- W fragments: f16 hi only (2-term split), register-resident ----
    uint32_t whi[4][4];
    {
        const float* r0 = W_hh + (jb + g) * 64;
        const float* r1 = W_hh + (jb + 8 + g) * 64;
        #pragma unroll
        for (int kt = 0; kt < 4; kt++) {
            const int k0 = kt * 16 + 2 * tg;
            whi[kt][0] = pack_h2(r0[k0],     r0[k0 + 1]);
            whi[kt][1] = pack_h2(r1[k0],     r1[k0 + 1]);
            whi[kt][2] = pack_h2(r0[k0 + 8], r0[k0 + 9]);
            whi[kt][3] = pack_h2(r1[k0 + 8], r1[k0 + 9]);
        }
    }

    // ---- act identities: thread owns unit n for 2 local cols per group ----
    const int n  = tid & 63;
    const int cl = tid >> 6;                    // 0..7 (local col base)
    float wiA[4], wiB[4], bia[4];
    #pragma unroll
    for (int q = 0; q < 4; q++) {
        int j = q * 64 + n;
        wiA[q] = W_ih[j * 2 + 0];
        wiB[q] = W_ih[j * 2 + 1];
        bia[q] = b_ih[j] + b_hh[j];
    }
    float cA[2] = {0.f, 0.f}, cB[2] = {0.f, 0.f};
    float hA[2] = {0.f, 0.f}, hB[2] = {0.f, 0.f};

    // h0 = 0
    for (int i = tid; i < NROW * HB_PAD / 2; i += NTH) {
        ((uint32_t*)hbhi)[i] = 0u;
        ((uint32_t*)hblo)[i] = 0u;
    }

    // ---- MMA phase for batch group grp: D[16 gates x 16 rows]x... ----
    auto mma_phase = [&](int grp) {
        #pragma unroll
        for (int nt = 0; nt < 2; nt++) {
            const int b = grp * 16 + nt * 8 + g;
            const __half* hh = hbhi[b];
            const __half* hl = hblo[b];
            float d[4] = {0.f, 0.f, 0.f, 0.f};
            #pragma unroll
            for (int kt = 0; kt < 4; kt++) {
                const int k0 = kt * 16 + 2 * tg;
                uint32_t bh0 = *(const uint32_t*)(hh + k0);
                uint32_t bh1 = *(const uint32_t*)(hh + k0 + 8);
                mma_f16(d, whi[kt], bh0, bh1);
            }
            #pragma unroll
            for (int kt = 0; kt < 4; kt++) {
                const int k0 = kt * 16 + 2 * tg;
                uint32_t bl0 = *(const uint32_t*)(hl + k0);
                uint32_t bl1 = *(const uint32_t*)(hl + k0 + 8);
                mma_f16(d, whi[kt], bl0, bl1);
            }
            const int br = grp * 16 + nt * 8 + 2 * tg;
            gs2[br][jb + g]         = d[0];
            gs2[br + 1][jb + g]     = d[1];
            gs2[br][jb + 8 + g]     = d[2];
            gs2[br + 1][jb + 8 + g] = d[3];
        }
    };

    // ---- act phase for group grp at time s ----
    auto act_phase = [&](int grp, int s, float* c, float* hsave) {
        const int tcs  = s % CH;
        const int bufs = (s / CH) & 1;
        #pragma unroll
        for (int i = 0; i < 2; i++) {
            const int b = grp * 16 + cl + 8 * i;
            float2 xv = xs[bufs][b][tcs];
            float gi  = gs2[b][n]       + fmaf(xv.y, wiB[0], fmaf(xv.x, wiA[0], bia[0]));
            float gf  = gs2[b][64 + n]  + fmaf(xv.y, wiB[1], fmaf(xv.x, wiA[1], bia[1]));
            float gg  = gs2[b][128 + n] + fmaf(xv.y, wiB[2], fmaf(xv.x, wiA[2], bia[2]));
            float go_ = gs2[b][192 + n] + fmaf(xv.y, wiB[3], fmaf(xv.x, wiA[3], bia[3]));
            float iv = sigmoid_f(gi);
            float fv = sigmoid_f(gf);
            float ov = sigmoid_f(go_);
            float gv = tanh_f(gg);
            float cv = fmaf(fv, c[i], iv * gv);
            c[i] = cv;
            float h = ov * tanh_f(cv);
            hsave[i] = h;
            __half hh = __float2half_rn(h);
            hbhi[b][n] = hh;
            hblo[b][n] = __float2half_rn(h - __half2float(hh));
        }
    };

    for (int t = 0; t < T_LEN; t++) {
        const int tc = t % CH;
        __syncthreads();                        // h(t-1) + gs2 of t-1 settled
        if (tc == 0) {
            const int buf = (t / CH) & 1;       // act(t-1) reads the OTHER buf
            for (int idx = tid; idx < NROW * CH; idx += NTH) {
                int b = idx / CH, cc = idx - b * CH;
                xs[buf][b][cc] = *(const float2*)(x + ((row0 + b) * T_LEN + t + cc) * 2);
            }
        }
        // phase1: MMA_A(t) || act_B(t-1)
        mma_phase(0);
        if (t > 0) act_phase(1, t - 1, cB, hB);
        __syncthreads();
        // phase2: MMA_B(t) || act_A(t)
        mma_phase(1);
        act_phase(0, t, cA, hA);
    }
    __syncthreads();
    act_phase(1, T_LEN - 1, cB, hB);            // drain

    // ---- fc head: stage final h (fp32) into gs2 rows, reduce ----
    __syncthreads();
    #pragma unroll
    for (int i = 0; i < 2; i++) {
        gs2[cl + 8 * i][n]      = hA[i];        // group A rows 0-15
        gs2[16 + cl + 8 * i][n] = hB[i];        // group B rows 16-31
    }
    __syncthreads();
    if (tid < NROW) {
        float s = b_fc[0];
        #pragma unroll
        for (int k = 0; k < 64; k++)
            s = fmaf(gs2[tid][k], W_fc[k], s);
        out[row0 + tid] = s;
    }
}

extern "C" void kernel_launch(void* const* d_in, const int* in_sizes, int n_in,
                              void* d_out, int out_size) {
    const float* x    = (const float*)d_in[0];
    const float* W_ih = (const float*)d_in[1];
    const float* W_hh = (const float*)d_in[2];
    const float* b_ih = (const float*)d_in[3];
    const float* b_hh = (const float*)d_in[4];
    const float* W_fc = (const float*)d_in[5];
    const float* b_fc = (const float*)d_in[6];
    float* out = (float*)d_out;
    (void)in_sizes; (void)n_in; (void)out_size;

    lstm_mma<<<GRID, NTH>>>(x, W_ih, W_hh, b_ih, b_hh, W_fc, b_fc, out);
}

// round 13
// speedup vs baseline: 3.3805x; 1.0040x over previous
#include <cuda_runtime.h>
#include <cuda_fp16.h>
#include <cstdint>

// LSTM_21869973471591 — B=4096, T=200, IN=2, H=64 (gates 4H=256)
//
// R13 = R12 resubmitted verbatim (R12 bench was an infra failure: GB300
// container failed twice; no kernel signal). Changes vs R11:
//  (a) dual accumulators: hi-term and lo-term MMA chains accumulate into
//      separate d registers (chain 8 -> 4, ILP 2), summed at drain.
//  (b) all 16 B-fragments of a batch group (2 n-tiles x 4 kt x hi/lo)
//      prefetched into registers before the chains -> LDS latency overlaps
//      the previous tile's MMA chain.
//  Kept from R11: 2-term f16 split (Whi*hhi + Whi*hlo), A/B batch-group
//  act/MMA software pipeline, double-buffered x (CH=10), pads.

#define B_TOT 4096
#define T_LEN 200
#define NROW  32
#define NTH   512
#define GRID  (B_TOT / NROW)   // 128
#define CH    10               // x staging chunk (200 % 10 == 0)

#define GS_PAD 260             // floats per gs2 row; 260 % 16 == 4 -> drain conflict-free
#define HB_PAD 72              // halfs per h row (144 B, frag loads conflict-free)

__device__ __forceinline__ void mma_f16(float d[4], const uint32_t a[4],
                                        uint32_t b0, uint32_t b1) {
    asm volatile(
        "mma.sync.aligned.m16n8k16.row.col.f32.f16.f16.f32 "
        "{%0,%1,%2,%3}, {%4,%5,%6,%7}, {%8,%9}, {%0,%1,%2,%3};"
        : "+f"(d[0]), "+f"(d[1]), "+f"(d[2]), "+f"(d[3])
        : "r"(a[0]), "r"(a[1]), "r"(a[2]), "r"(a[3]), "r"(b0), "r"(b1));
}

__device__ __forceinline__ uint16_t h_bits(__half h) {
    return *reinterpret_cast<uint16_t*>(&h);
}
__device__ __forceinline__ uint32_t pack_h2(float a, float b) {
    __half ah = __float2half_rn(a), bh = __float2half_rn(b);
    return ((uint32_t)h_bits(bh) << 16) | h_bits(ah);
}

__device__ __forceinline__ float fast_rcp(float x) {
    float r; asm("rcp.approx.f32 %0, %1;" : "=f"(r) : "f"(x)); return r;
}
__device__ __forceinline__ float fast_ex2(float x) {
    float r; asm("ex2.approx.f32 %0, %1;" : "=f"(r) : "f"(x)); return r;
}
__device__ __forceinline__ float sigmoid_f(float x) {
    float e = fast_ex2(-1.4426950408889634f * x);
    return fast_rcp(1.0f + e);
}
__device__ __forceinline__ float tanh_f(float x) {
    float e = fast_ex2(2.8853900817779268f * x);
    return fmaf(-2.0f, fast_rcp(1.0f + e), 1.0f);
}

__global__ __launch_bounds__(NTH)
void lstm_mma(const float* __restrict__ x,      // [B, T, 2]
              const float* __restrict__ W_ih,   // [256, 2]
              const float* __restrict__ W_hh,   // [256, 64]
              const float* __restrict__ b_ih,   // [256]
              const float* __restrict__ b_hh,   // [256]
              const float* __restrict__ W_fc,   // [1, 64]
              const float* __restrict__ b_fc,   // [1]
              float* __restrict__ out)          // [B, 1]
{
    __shared__ float  gs2[NROW][GS_PAD];        // gates [b][j]    33280 B
    __shared__ __half hbhi[NROW][HB_PAD];       // h hi  [b][k]     4608 B
    __shared__ __half hblo[NROW][HB_PAD];       // h lo  [b][k]     4608 B
    __shared__ float2 xs[2][NROW][CH];          // double-buffered  5120 B

    const int tid  = threadIdx.x;
    const int warp = tid >> 5;
    const int lane = tid & 31;
    const int g    = lane >> 2;                 // fragment group row
    const int tg   = lane & 3;                  // thread-in-group
    const int jb   = warp * 16;                 // this warp's gate-row base
    const int row0 = blockIdx.x * NROW;

    // ---- W fragments: f16 hi only (2-term split), register-resident ----
    uint32_t whi[4][4];
    {
        const float* r0 = W_hh + (jb + g) * 64;
        const float* r1 = W_hh + (jb + 8 + g) * 64;
        #pragma unroll
        for (int kt = 0; kt < 4; kt++) {
            const int k0 = kt * 16 + 2 * tg;
            whi[kt][0] = pack_h2(r0[k0],     r0[k0 + 1]);
            whi[kt][1] = pack_h2(r1[k0],     r1[k0 + 1]);
            whi[kt][2] = pack_h2(r0[k0 + 8], r0[k0 + 9]);
            whi[kt][3] = pack_h2(r1[k0 + 8], r1[k0 + 9]);
        }
    }

    // ---- act identities: thread owns unit n for 2 local cols per group ----
    const int n  = tid & 63;
    const int cl = tid >> 6;                    // 0..7 (local col base)
    float wiA[4], wiB[4], bia[4];
    #pragma unroll
    for (int q = 0; q < 4; q++) {
        int j = q * 64 + n;
        wiA[q] = W_ih[j * 2 + 0];
        wiB[q] = W_ih[j * 2 + 1];
        bia[q] = b_ih[j] + b_hh[j];
    }
    float cA[2] = {0.f, 0.f}, cB[2] = {0.f, 0.f};
    float hA[2] = {0.f, 0.f}, hB[2] = {0.f, 0.f};

    // h0 = 0
    for (int i = tid; i < NROW * HB_PAD / 2; i += NTH) {
        ((uint32_t*)hbhi)[i] = 0u;
        ((uint32_t*)hblo)[i] = 0u;
    }

    // ---- MMA phase for batch group grp: prefetch all frags, dual-acc ----
    auto mma_phase = [&](int grp) {
        // prefetch 16 B fragments (2 n-tiles x 4 kt x {hi,lo} pairs)
        uint32_t bh[2][4][2], bl[2][4][2];
        #pragma unroll
        for (int nt = 0; nt < 2; nt++) {
            const int b = grp * 16 + nt * 8 + g;
            const __half* hh = hbhi[b];
            const __half* hl = hblo[b];
            #pragma unroll
            for (int kt = 0; kt < 4; kt++) {
                const int k0 = kt * 16 + 2 * tg;
                bh[nt][kt][0] = *(const uint32_t*)(hh + k0);
                bh[nt][kt][1] = *(const uint32_t*)(hh + k0 + 8);
                bl[nt][kt][0] = *(const uint32_t*)(hl + k0);
                bl[nt][kt][1] = *(const uint32_t*)(hl + k0 + 8);
            }
        }
        #pragma unroll
        for (int nt = 0; nt < 2; nt++) {
            float dh[4] = {0.f, 0.f, 0.f, 0.f};
            float dl[4] = {0.f, 0.f, 0.f, 0.f};
            #pragma unroll
            for (int kt = 0; kt < 4; kt++) {       // two independent chains
                mma_f16(dh, whi[kt], bh[nt][kt][0], bh[nt][kt][1]);
                mma_f16(dl, whi[kt], bl[nt][kt][0], bl[nt][kt][1]);
            }
            const int br = grp * 16 + nt * 8 + 2 * tg;
            gs2[br][jb + g]         = dh[0] + dl[0];
            gs2[br + 1][jb + g]     = dh[1] + dl[1];
            gs2[br][jb + 8 + g]     = dh[2] + dl[2];
            gs2[br + 1][jb + 8 + g] = dh[3] + dl[3];
        }
    };

    // ---- act phase for group grp at time s ----
    auto act_phase = [&](int grp, int s, float* c, float* hsave) {
        const int tcs  = s % CH;
        const int bufs = (s / CH) & 1;
        #pragma unroll
        for (int i = 0; i < 2; i++) {
            const int b = grp * 16 + cl + 8 * i;
            float2 xv = xs[bufs][b][tcs];
            float gi  = gs2[b][n]       + fmaf(xv.y, wiB[0], fmaf(xv.x, wiA[0], bia[0]));
            float gf  = gs2[b][64 + n]  + fmaf(xv.y, wiB[1], fmaf(xv.x, wiA[1], bia[1]));
            float gg  = gs2[b][128 + n] + fmaf(xv.y, wiB[2], fmaf(xv.x, wiA[2], bia[2]));
            float go_ = gs2[b][192 + n] + fmaf(xv.y, wiB[3], fmaf(xv.x, wiA[3], bia[3]));
            float iv = sigmoid_f(gi);
            float fv = sigmoid_f(gf);
            float ov = sigmoid_f(go_);
            float gv = tanh_f(gg);
            float cv = fmaf(fv, c[i], iv * gv);
            c[i] = cv;
            float h = ov * tanh_f(cv);
            hsave[i] = h;
            __half hh = __float2half_rn(h);
            hbhi[b][n] = hh;
            hblo[b][n] = __float2half_rn(h - __half2float(hh));
        }
    };

    for (int t = 0; t < T_LEN; t++) {
        const int tc = t % CH;
        __syncthreads();                        // h(t-1) + gs2 of t-1 settled
        if (tc == 0) {
            const int buf = (t / CH) & 1;       // act(t-1) reads the OTHER buf
            for (int idx = tid; idx < NROW * CH; idx += NTH) {
                int b = idx / CH, cc = idx - b * CH;
                xs[buf][b][cc] = *(const float2*)(x + ((row0 + b) * T_LEN + t + cc) * 2);
            }
        }
        // phase1: MMA_A(t) || act_B(t-1)
        mma_phase(0);
        if (t > 0) act_phase(1, t - 1, cB, hB);
        __syncthreads();
        // phase2: MMA_B(t) || act_A(t)
        mma_phase(1);
        act_phase(0, t, cA, hA);
    }
    __syncthreads();
    act_phase(1, T_LEN - 1, cB, hB);            // drain

    // ---- fc head: stage final h (fp32) into gs2 rows, reduce ----
    __syncthreads();
    #pragma unroll
    for (int i = 0; i < 2; i++) {
        gs2[cl + 8 * i][n]      = hA[i];        // group A rows 0-15
        gs2[16 + cl + 8 * i][n] = hB[i];        // group B rows 16-31
    }
    __syncthreads();
    if (tid < NROW) {
        float s = b_fc[0];
        #pragma unroll
        for (int k = 0; k < 64; k++)
            s = fmaf(gs2[tid][k], W_fc[k], s);
        out[row0 + tid] = s;
    }
}

extern "C" void kernel_launch(void* const* d_in, const int* in_sizes, int n_in,
                              void* d_out, int out_size) {
    const float* x    = (const float*)d_in[0];
    const float* W_ih = (const float*)d_in[1];
    const float* W_hh = (const float*)d_in[2];
    const float* b_ih = (const float*)d_in[3];
    const float* b_hh = (const float*)d_in[4];
    const float* W_fc = (const float*)d_in[5];
    const float* b_fc = (const float*)d_in[6];
    float* out = (float*)d_out;
    (void)in_sizes; (void)n_in; (void)out_size;

    lstm_mma<<<GRID, NTH>>>(x, W_ih, W_hh, b_ih, b_hh, W_fc, b_fc, out);
}

// round 15
// speedup vs baseline: 4.1185x; 1.2183x over previous
#include <cuda_runtime.h>
#include <cuda_fp16.h>
#include <cstdint>

// LSTM_21869973471591 — B=4096, T=200, IN=2, H=64 (gates 4H=256)
//
// R15 = R14 resubmitted verbatim (R14 bench was an infra failure: GB300
// container failed twice; no kernel signal — same as R12, whose verbatim
// resubmit benched cleanly).
//
// R14: fused mapping — D fragments land exactly where act needs them.
// Warp w = (batch half bh=w>>3, unit block wu=w&7). Its two A-tiles are
// gate rows {i,f} = {8wu+g, 64+8wu+g} and {g,o} = {128+8wu+g, 192+8wu+g}.
// With the m16n8k16 D layout (thread (g,tg): rows g,g+8 x cols 2tg,2tg+1),
// thread (g,tg) holds gi,gf,gg,go for unit u=8wu+g, batch cols 2tg/2tg+1:
// activation is fully in-register.
//  - gs2 smem staging DELETED (was 33KB + 16 smem ops + alu per thread-step)
//  - 1 barrier per step (h double-buffered); +1 per CH=10 steps (x staging)
//  - x-gates injected as the initial value of the hi accumulator
//  - both A-tiles share the same B fragments (same batch x k) -> LDS flat
// Kept: 2-term f16 split (Whi*hhi + Whi*hlo, rel_err 1.15e-5 proven),
// grid 128 x NROW=32, 512 threads, dual hi/lo accumulator chains.

#define B_TOT 4096
#define T_LEN 200
#define NROW  32
#define NTH   512
#define GRID  (B_TOT / NROW)   // 128
#define CH    10               // x staging chunk (200 % 10 == 0)
#define HB_PAD 72              // halfs per h row

__device__ __forceinline__ void mma_f16(float d[4], const uint32_t a[4],
                                        uint32_t b0, uint32_t b1) {
    asm volatile(
        "mma.sync.aligned.m16n8k16.row.col.f32.f16.f16.f32 "
        "{%0,%1,%2,%3}, {%4,%5,%6,%7}, {%8,%9}, {%0,%1,%2,%3};"
        : "+f"(d[0]), "+f"(d[1]), "+f"(d[2]), "+f"(d[3])
        : "r"(a[0]), "r"(a[1]), "r"(a[2]), "r"(a[3]), "r"(b0), "r"(b1));
}

__device__ __forceinline__ uint16_t h_bits(__half h) {
    return *reinterpret_cast<uint16_t*>(&h);
}
__device__ __forceinline__ uint32_t pack_h2(float a, float b) {
    __half ah = __float2half_rn(a), bh = __float2half_rn(b);
    return ((uint32_t)h_bits(bh) << 16) | h_bits(ah);
}

__device__ __forceinline__ float fast_rcp(float x) {
    float r; asm("rcp.approx.f32 %0, %1;" : "=f"(r) : "f"(x)); return r;
}
__device__ __forceinline__ float fast_ex2(float x) {
    float r; asm("ex2.approx.f32 %0, %1;" : "=f"(r) : "f"(x)); return r;
}
__device__ __forceinline__ float sigmoid_f(float x) {
    float e = fast_ex2(-1.4426950408889634f * x);
    return fast_rcp(1.0f + e);
}
__device__ __forceinline__ float tanh_f(float x) {
    float e = fast_ex2(2.8853900817779268f * x);
    return fmaf(-2.0f, fast_rcp(1.0f + e), 1.0f);
}

__global__ __launch_bounds__(NTH)
void lstm_mma(const float* __restrict__ x,      // [B, T, 2]
              const float* __restrict__ W_ih,   // [256, 2]
              const float* __restrict__ W_hh,   // [256, 64]
              const float* __restrict__ b_ih,   // [256]
              const float* __restrict__ b_hh,   // [256]
              const float* __restrict__ W_fc,   // [1, 64]
              const float* __restrict__ b_fc,   // [1]
              float* __restrict__ out)          // [B, 1]
{
    __shared__ __half hbhi[2][NROW][HB_PAD];    // h hi, double-buffered  9216 B
    __shared__ __half hblo[2][NROW][HB_PAD];    // h lo                   9216 B
    __shared__ float2 xs[NROW][CH];             //                        2560 B
    __shared__ float  hf[NROW][65];             // fc staging             8320 B

    const int tid  = threadIdx.x;
    const int warp = tid >> 5;
    const int lane = tid & 31;
    const int g    = lane >> 2;                 // fragment group row
    const int tg   = lane & 3;                  // thread-in-group
    const int bh2  = warp >> 3;                 // batch half 0/1
    const int wu   = warp & 7;                  // unit block
    const int u    = wu * 8 + g;                // hidden unit owned by thread
    const int row0 = blockIdx.x * NROW;

    // ---- W fragments, tiles X={i,f} and Y={g,o} for units [8wu, 8wu+8) ----
    // A-frag rows (proven R10): a0=(row g,k0..k0+1) a1=(row g+8) a2=(g,k0+8) a3=(g+8,k0+8)
    uint32_t wx[4][4], wy[4][4];
    {
        const float* ri = W_hh + (u)        * 64;   // gate i row
        const float* rf = W_hh + (64 + u)   * 64;   // gate f row
        const float* rg = W_hh + (128 + u)  * 64;   // gate g row
        const float* ro = W_hh + (192 + u)  * 64;   // gate o row
        #pragma unroll
        for (int kt = 0; kt < 4; kt++) {
            const int k0 = kt * 16 + 2 * tg;
            wx[kt][0] = pack_h2(ri[k0],     ri[k0 + 1]);
            wx[kt][1] = pack_h2(rf[k0],     rf[k0 + 1]);
            wx[kt][2] = pack_h2(ri[k0 + 8], ri[k0 + 9]);
            wx[kt][3] = pack_h2(rf[k0 + 8], rf[k0 + 9]);
            wy[kt][0] = pack_h2(rg[k0],     rg[k0 + 1]);
            wy[kt][1] = pack_h2(ro[k0],     ro[k0 + 1]);
            wy[kt][2] = pack_h2(rg[k0 + 8], rg[k0 + 9]);
            wy[kt][3] = pack_h2(ro[k0 + 8], ro[k0 + 9]);
        }
    }

    // per-unit x-path constants for gates i,f,g,o of unit u
    float wA[4], wB[4], bb_[4];
    #pragma unroll
    for (int q = 0; q < 4; q++) {
        int j = q * 64 + u;
        wA[q]  = W_ih[j * 2 + 0];
        wB[q]  = W_ih[j * 2 + 1];
        bb_[q] = b_ih[j] + b_hh[j];
    }

    float c[4]  = {0.f, 0.f, 0.f, 0.f};        // c-state: [nt*2 + colparity]
    float hv[4] = {0.f, 0.f, 0.f, 0.f};        // last h (for fc head)

    // h0 = 0 (both buffers)
    for (int i = tid; i < 2 * NROW * HB_PAD / 2; i += NTH) {
        ((uint32_t*)hbhi)[i] = 0u;
        ((uint32_t*)hblo)[i] = 0u;
    }
    __syncthreads();

    for (int t = 0; t < T_LEN; t++) {
        const int tc = t % CH;
        if (tc == 0) {
            // stage x[t..t+CH); prior reads finished before last step's barrier
            for (int idx = tid; idx < NROW * CH; idx += NTH) {
                int b = idx / CH, cc = idx - b * CH;
                xs[b][cc] = *(const float2*)(x + ((row0 + b) * T_LEN + t + cc) * 2);
            }
            __syncthreads();
        }

        const int p = t & 1;                    // read h buffer
        const int q = p ^ 1;                    // write h buffer

        #pragma unroll
        for (int nt = 0; nt < 2; nt++) {
            const int bb = bh2 * 16 + nt * 8;   // batch base of this n-tile
            // B fragments (shared by tiles X and Y) — proven R10 layout
            const __half* hh = hbhi[p][bb + g];
            const __half* hl = hblo[p][bb + g];
            uint32_t bhf[4][2], blf[4][2];
            #pragma unroll
            for (int kt = 0; kt < 4; kt++) {
                const int k0 = kt * 16 + 2 * tg;
                bhf[kt][0] = *(const uint32_t*)(hh + k0);
                bhf[kt][1] = *(const uint32_t*)(hh + k0 + 8);
                blf[kt][0] = *(const uint32_t*)(hl + k0);
                blf[kt][1] = *(const uint32_t*)(hl + k0 + 8);
            }
            // x-gate injection: initial value of the hi accumulators
            const int b0 = bb + 2 * tg;
            float2 x0 = xs[b0][tc], x1 = xs[b0 + 1][tc];
            float dxh[4], dyh[4];
            dxh[0] = fmaf(x0.y, wB[0], fmaf(x0.x, wA[0], bb_[0]));  // gi @ b0
            dxh[1] = fmaf(x1.y, wB[0], fmaf(x1.x, wA[0], bb_[0]));  // gi @ b0+1
            dxh[2] = fmaf(x0.y, wB[1], fmaf(x0.x, wA[1], bb_[1]));  // gf @ b0
            dxh[3] = fmaf(x1.y, wB[1], fmaf(x1.x, wA[1], bb_[1]));  // gf @ b0+1
            dyh[0] = fmaf(x0.y, wB[2], fmaf(x0.x, wA[2], bb_[2]));  // gg @ b0
            dyh[1] = fmaf(x1.y, wB[2], fmaf(x1.x, wA[2], bb_[2]));  // gg @ b0+1
            dyh[2] = fmaf(x0.y, wB[3], fmaf(x0.x, wA[3], bb_[3]));  // go @ b0
            dyh[3] = fmaf(x1.y, wB[3], fmaf(x1.x, wA[3], bb_[3]));  // go @ b0+1
            float dxl[4] = {0.f, 0.f, 0.f, 0.f};
            float dyl[4] = {0.f, 0.f, 0.f, 0.f};
            // 4 independent MMA chains (X/Y x hi/lo)
            #pragma unroll
            for (int kt = 0; kt < 4; kt++) {
                mma_f16(dxh, wx[kt], bhf[kt][0], bhf[kt][1]);
                mma_f16(dxl, wx[kt], blf[kt][0], blf[kt][1]);
                mma_f16(dyh, wy[kt], bhf[kt][0], bhf[kt][1]);
                mma_f16(dyl, wy[kt], blf[kt][0], blf[kt][1]);
            }
            // ---- activation, fully in-register (2 batch cols) ----
            #pragma unroll
            for (int e = 0; e < 2; e++) {
                const int bcol = b0 + e;
                float gi  = dxh[0 + e] + dxl[0 + e];
                float gf  = dxh[2 + e] + dxl[2 + e];
                float gg  = dyh[0 + e] + dyl[0 + e];
                float go_ = dyh[2 + e] + dyl[2 + e];
                float iv = sigmoid_f(gi);
                float fv = sigmoid_f(gf);
                float ov = sigmoid_f(go_);
                float gv = tanh_f(gg);
                const int ci = nt * 2 + e;
                float cv = fmaf(fv, c[ci], iv * gv);
                c[ci] = cv;
                float h = ov * tanh_f(cv);
                hv[ci] = h;
                __half hhp = __float2half_rn(h);
                hbhi[q][bcol][u] = hhp;
                hblo[q][bcol][u] = __float2half_rn(h - __half2float(hhp));
            }
        }
        __syncthreads();                        // h(t) published
    }

    // ---- fc head ----
    #pragma unroll
    for (int nt = 0; nt < 2; nt++) {
        const int b0 = bh2 * 16 + nt * 8 + 2 * tg;
        hf[b0][u]     = hv[nt * 2 + 0];
        hf[b0 + 1][u] = hv[nt * 2 + 1];
    }
    __syncthreads();
    if (tid < NROW) {
        float s = b_fc[0];
        #pragma unroll
        for (int k = 0; k < 64; k++)
            s = fmaf(hf[tid][k], W_fc[k], s);
        out[row0 + tid] = s;
    }
}

extern "C" void kernel_launch(void* const* d_in, const int* in_sizes, int n_in,
                              void* d_out, int out_size) {
    const float* x    = (const float*)d_in[0];
    const float* W_ih = (const float*)d_in[1];
    const float* W_hh = (const float*)d_in[2];
    const float* b_ih = (const float*)d_in[3];
    const float* b_hh = (const float*)d_in[4];
    const float* W_fc = (const float*)d_in[5];
    const float* b_fc = (const float*)d_in[6];
    float* out = (float*)d_out;
    (void)in_sizes; (void)n_in; (void)out_size;

    lstm_mma<<<GRID, NTH>>>(x, W_ih, W_hh, b_ih, b_hh, W_fc, b_fc, out);
}

// round 16
// speedup vs baseline: 4.4611x; 1.0832x over previous
#include <cuda_runtime.h>
#include <cuda_fp16.h>
#include <cstdint>

// LSTM_21869973471591 — B=4096, T=200, IN=2, H=64 (gates 4H=256)
//
// R16 = R15 with half-size CTAs to fill the chip and double scheduler depth:
//   NTH 512->256, NROW 32->16, grid 128->256.
//   - 148-SM part: grid 128 left 20 SMs idle; grid 256 -> one full wave
//     (108 SMs x 2 CTAs + 40 x 1), regs ~99 & smem ~15KB allow 2 CTAs/SM.
//   - two INDEPENDENT CTAs per SM interleave: one CTA's barrier/MMA-latency
//     holes are filled by the other's MUFU/FMA work.
// Mapping (from R15, proven): warp w = unit block; thread (g,tg) owns
// hidden unit u=8w+g for batch cols 2tg/2tg+1 of each n-tile; D fragment
// = {gi,gf,gg,go} directly -> activation fully in-register; no gate smem;
// 1 barrier/step; x-gates seeded into the hi accumulators; 2-term f16
// split (rel_err 1.150e-5 proven — must not change).

#define B_TOT 4096
#define T_LEN 200
#define NROW  16
#define NTH   256
#define GRID  (B_TOT / NROW)   // 256
#define CH    10               // x staging chunk (200 % 10 == 0)
#define HB_PAD 72              // halfs per h row

__device__ __forceinline__ void mma_f16(float d[4], const uint32_t a[4],
                                        uint32_t b0, uint32_t b1) {
    asm volatile(
        "mma.sync.aligned.m16n8k16.row.col.f32.f16.f16.f32 "
        "{%0,%1,%2,%3}, {%4,%5,%6,%7}, {%8,%9}, {%0,%1,%2,%3};"
        : "+f"(d[0]), "+f"(d[1]), "+f"(d[2]), "+f"(d[3])
        : "r"(a[0]), "r"(a[1]), "r"(a[2]), "r"(a[3]), "r"(b0), "r"(b1));
}

__device__ __forceinline__ uint16_t h_bits(__half h) {
    return *reinterpret_cast<uint16_t*>(&h);
}
__device__ __forceinline__ uint32_t pack_h2(float a, float b) {
    __half ah = __float2half_rn(a), bh = __float2half_rn(b);
    return ((uint32_t)h_bits(bh) << 16) | h_bits(ah);
}

__device__ __forceinline__ float fast_rcp(float x) {
    float r; asm("rcp.approx.f32 %0, %1;" : "=f"(r) : "f"(x)); return r;
}
__device__ __forceinline__ float fast_ex2(float x) {
    float r; asm("ex2.approx.f32 %0, %1;" : "=f"(r) : "f"(x)); return r;
}
__device__ __forceinline__ float sigmoid_f(float x) {
    float e = fast_ex2(-1.4426950408889634f * x);
    return fast_rcp(1.0f + e);
}
__device__ __forceinline__ float tanh_f(float x) {
    float e = fast_ex2(2.8853900817779268f * x);
    return fmaf(-2.0f, fast_rcp(1.0f + e), 1.0f);
}

__global__ __launch_bounds__(NTH, 2)
void lstm_mma(const float* __restrict__ x,      // [B, T, 2]
              const float* __restrict__ W_ih,   // [256, 2]
              const float* __restrict__ W_hh,   // [256, 64]
              const float* __restrict__ b_ih,   // [256]
              const float* __restrict__ b_hh,   // [256]
              const float* __restrict__ W_fc,   // [1, 64]
              const float* __restrict__ b_fc,   // [1]
              float* __restrict__ out)          // [B, 1]
{
    __shared__ __half hbhi[2][NROW][HB_PAD];    // h hi, double-buffered  4608 B
    __shared__ __half hblo[2][NROW][HB_PAD];    // h lo                   4608 B
    __shared__ float2 xs[NROW][CH];             //                        1280 B
    __shared__ float  hf[NROW][65];             // fc staging             4160 B

    const int tid  = threadIdx.x;
    const int warp = tid >> 5;                  // unit block 0..7
    const int lane = tid & 31;
    const int g    = lane >> 2;                 // fragment group row
    const int tg   = lane & 3;                  // thread-in-group
    const int u    = warp * 8 + g;              // hidden unit owned by thread
    const int row0 = blockIdx.x * NROW;

    // ---- W fragments, tiles X={i,f} and Y={g,o} for units [8w, 8w+8) ----
    uint32_t wx[4][4], wy[4][4];
    {
        const float* ri = W_hh + (u)        * 64;
        const float* rf = W_hh + (64 + u)   * 64;
        const float* rg = W_hh + (128 + u)  * 64;
        const float* ro = W_hh + (192 + u)  * 64;
        #pragma unroll
        for (int kt = 0; kt < 4; kt++) {
            const int k0 = kt * 16 + 2 * tg;
            wx[kt][0] = pack_h2(ri[k0],     ri[k0 + 1]);
            wx[kt][1] = pack_h2(rf[k0],     rf[k0 + 1]);
            wx[kt][2] = pack_h2(ri[k0 + 8], ri[k0 + 9]);
            wx[kt][3] = pack_h2(rf[k0 + 8], rf[k0 + 9]);
            wy[kt][0] = pack_h2(rg[k0],     rg[k0 + 1]);
            wy[kt][1] = pack_h2(ro[k0],     ro[k0 + 1]);
            wy[kt][2] = pack_h2(rg[k0 + 8], rg[k0 + 9]);
            wy[kt][3] = pack_h2(ro[k0 + 8], ro[k0 + 9]);
        }
    }

    // per-unit x-path constants for gates i,f,g,o of unit u
    float wA[4], wB[4], bb_[4];
    #pragma unroll
    for (int q2 = 0; q2 < 4; q2++) {
        int j = q2 * 64 + u;
        wA[q2]  = W_ih[j * 2 + 0];
        wB[q2]  = W_ih[j * 2 + 1];
        bb_[q2] = b_ih[j] + b_hh[j];
    }

    float c[4]  = {0.f, 0.f, 0.f, 0.f};        // c-state: [nt*2 + colparity]
    float hv[4] = {0.f, 0.f, 0.f, 0.f};        // last h (for fc head)

    // h0 = 0 (both buffers)
    for (int i = tid; i < 2 * NROW * HB_PAD / 2; i += NTH) {
        ((uint32_t*)hbhi)[i] = 0u;
        ((uint32_t*)hblo)[i] = 0u;
    }
    __syncthreads();

    for (int t = 0; t < T_LEN; t++) {
        const int tc = t % CH;
        if (tc == 0) {
            for (int idx = tid; idx < NROW * CH; idx += NTH) {
                int b = idx / CH, cc = idx - b * CH;
                xs[b][cc] = *(const float2*)(x + ((row0 + b) * T_LEN + t + cc) * 2);
            }
            __syncthreads();
        }

        const int p = t & 1;                    // read h buffer
        const int q = p ^ 1;                    // write h buffer

        #pragma unroll
        for (int nt = 0; nt < 2; nt++) {
            const int bb = nt * 8;              // batch base of this n-tile
            const __half* hh = hbhi[p][bb + g];
            const __half* hl = hblo[p][bb + g];
            uint32_t bhf[4][2], blf[4][2];
            #pragma unroll
            for (int kt = 0; kt < 4; kt++) {
                const int k0 = kt * 16 + 2 * tg;
                bhf[kt][0] = *(const uint32_t*)(hh + k0);
                bhf[kt][1] = *(const uint32_t*)(hh + k0 + 8);
                blf[kt][0] = *(const uint32_t*)(hl + k0);
                blf[kt][1] = *(const uint32_t*)(hl + k0 + 8);
            }
            // x-gate injection: initial value of the hi accumulators
            const int b0 = bb + 2 * tg;
            float2 x0 = xs[b0][tc], x1 = xs[b0 + 1][tc];
            float dxh[4], dyh[4];
            dxh[0] = fmaf(x0.y, wB[0], fmaf(x0.x, wA[0], bb_[0]));  // gi @ b0
            dxh[1] = fmaf(x1.y, wB[0], fmaf(x1.x, wA[0], bb_[0]));  // gi @ b0+1
            dxh[2] = fmaf(x0.y, wB[1], fmaf(x0.x, wA[1], bb_[1]));  // gf @ b0
            dxh[3] = fmaf(x1.y, wB[1], fmaf(x1.x, wA[1], bb_[1]));  // gf @ b0+1
            dyh[0] = fmaf(x0.y, wB[2], fmaf(x0.x, wA[2], bb_[2]));  // gg @ b0
            dyh[1] = fmaf(x1.y, wB[2], fmaf(x1.x, wA[2], bb_[2]));  // gg @ b0+1
            dyh[2] = fmaf(x0.y, wB[3], fmaf(x0.x, wA[3], bb_[3]));  // go @ b0
            dyh[3] = fmaf(x1.y, wB[3], fmaf(x1.x, wA[3], bb_[3]));  // go @ b0+1
            float dxl[4] = {0.f, 0.f, 0.f, 0.f};
            float dyl[4] = {0.f, 0.f, 0.f, 0.f};
            // 4 independent MMA chains (X/Y x hi/lo)
            #pragma unroll
            for (int kt = 0; kt < 4; kt++) {
                mma_f16(dxh, wx[kt], bhf[kt][0], bhf[kt][1]);
                mma_f16(dxl, wx[kt], blf[kt][0], blf[kt][1]);
                mma_f16(dyh, wy[kt], bhf[kt][0], bhf[kt][1]);
                mma_f16(dyl, wy[kt], blf[kt][0], blf[kt][1]);
            }
            // ---- activation, fully in-register (2 batch cols) ----
            #pragma unroll
            for (int e = 0; e < 2; e++) {
                const int bcol = b0 + e;
                float gi  = dxh[0 + e] + dxl[0 + e];
                float gf  = dxh[2 + e] + dxl[2 + e];
                float gg  = dyh[0 + e] + dyl[0 + e];
                float go_ = dyh[2 + e] + dyl[2 + e];
                float iv = sigmoid_f(gi);
                float fv = sigmoid_f(gf);
                float ov = sigmoid_f(go_);
                float gv = tanh_f(gg);
                const int ci = nt * 2 + e;
                float cv = fmaf(fv, c[ci], iv * gv);
                c[ci] = cv;
                float h = ov * tanh_f(cv);
                hv[ci] = h;
                __half hhp = __float2half_rn(h);
                hbhi[q][bcol][u] = hhp;
                hblo[q][bcol][u] = __float2half_rn(h - __half2float(hhp));
            }
        }
        __syncthreads();                        // h(t) published
    }

    // ---- fc head ----
    #pragma unroll
    for (int nt = 0; nt < 2; nt++) {
        const int b0 = nt * 8 + 2 * tg;
        hf[b0][u]     = hv[nt * 2 + 0];
        hf[b0 + 1][u] = hv[nt * 2 + 1];
    }
    __syncthreads();
    if (tid < NROW) {
        float s = b_fc[0];
        #pragma unroll
        for (int k = 0; k < 64; k++)
            s = fmaf(hf[tid][k], W_fc[k], s);
        out[row0 + tid] = s;
    }
}

extern "C" void kernel_launch(void* const* d_in, const int* in_sizes, int n_in,
                              void* d_out, int out_size) {
    const float* x    = (const float*)d_in[0];
    const float* W_ih = (const float*)d_in[1];
    const float* W_hh = (const float*)d_in[2];
    const float* b_ih = (const float*)d_in[3];
    const float* b_hh = (const float*)d_in[4];
    const float* W_fc = (const float*)d_in[5];
    const float* b_fc = (const float*)d_in[6];
    float* out = (float*)d_out;
    (void)in_sizes; (void)n_in; (void)out_size;

    lstm_mma<<<GRID, NTH>>>(x, W_ih, W_hh, b_ih, b_hh, W_fc, b_fc, out);
}

// round 17
// speedup vs baseline: 5.4566x; 1.2232x over previous
#include <cuda_runtime.h>
#include <cuda_fp16.h>
#include <cstdint>

// LSTM_21869973471591 — B=4096, T=200, IN=2, H=64 (gates 4H=256)
//
// R17 = R16 minus the h-lo correction term: h stored as plain f16, single
// MMA chain per tile pair (W_hi f16 x h f16, fp32 accum).
// Precision argument (empirical): R11 showed a static 2.4e-4 W perturbation
// attenuates ~21x to 1.15e-5 at the output. f16 h-rounding injects ~4.9e-4
// random zero-mean noise/step into a contractive recurrent map (gate scale
// 1/8, ||J||~0.5) -> expected final rel_err 3e-5..1e-4, << 1e-3.
// Payoff: MMA 16->8 per step, LDS 32->16, lo pack/stores deleted, regs down.
// Kept from R15/R16 (proven): fused D-fragment mapping (thread (g,tg) owns
// {gi,gf,gg,go} of unit u=8w+g for batch cols 2tg/2tg+1), in-register
// activation, 1 barrier/step, x-gates seeded into accumulators,
// NTH=256 / NROW=16 / grid=256 (2 CTAs on 108 SMs).

#define B_TOT 4096
#define T_LEN 200
#define NROW  16
#define NTH   256
#define GRID  (B_TOT / NROW)   // 256
#define CH    10               // x staging chunk (200 % 10 == 0)
#define HB_PAD 72              // halfs per h row

__device__ __forceinline__ void mma_f16(float d[4], const uint32_t a[4],
                                        uint32_t b0, uint32_t b1) {
    asm volatile(
        "mma.sync.aligned.m16n8k16.row.col.f32.f16.f16.f32 "
        "{%0,%1,%2,%3}, {%4,%5,%6,%7}, {%8,%9}, {%0,%1,%2,%3};"
        : "+f"(d[0]), "+f"(d[1]), "+f"(d[2]), "+f"(d[3])
        : "r"(a[0]), "r"(a[1]), "r"(a[2]), "r"(a[3]), "r"(b0), "r"(b1));
}

__device__ __forceinline__ uint16_t h_bits(__half h) {
    return *reinterpret_cast<uint16_t*>(&h);
}
__device__ __forceinline__ uint32_t pack_h2(float a, float b) {
    __half ah = __float2half_rn(a), bh = __float2half_rn(b);
    return ((uint32_t)h_bits(bh) << 16) | h_bits(ah);
}

__device__ __forceinline__ float fast_rcp(float x) {
    float r; asm("rcp.approx.f32 %0, %1;" : "=f"(r) : "f"(x)); return r;
}
__device__ __forceinline__ float fast_ex2(float x) {
    float r; asm("ex2.approx.f32 %0, %1;" : "=f"(r) : "f"(x)); return r;
}
__device__ __forceinline__ float sigmoid_f(float x) {
    float e = fast_ex2(-1.4426950408889634f * x);
    return fast_rcp(1.0f + e);
}
__device__ __forceinline__ float tanh_f(float x) {
    float e = fast_ex2(2.8853900817779268f * x);
    return fmaf(-2.0f, fast_rcp(1.0f + e), 1.0f);
}

__global__ __launch_bounds__(NTH, 2)
void lstm_mma(const float* __restrict__ x,      // [B, T, 2]
              const float* __restrict__ W_ih,   // [256, 2]
              const float* __restrict__ W_hh,   // [256, 64]
              const float* __restrict__ b_ih,   // [256]
              const float* __restrict__ b_hh,   // [256]
              const float* __restrict__ W_fc,   // [1, 64]
              const float* __restrict__ b_fc,   // [1]
              float* __restrict__ out)          // [B, 1]
{
    __shared__ __half hb[2][NROW][HB_PAD];      // h (f16), double-buffered 4608 B
    __shared__ float2 xs[NROW][CH];             //                          1280 B
    __shared__ float  hf[NROW][65];             // fc staging               4160 B

    const int tid  = threadIdx.x;
    const int warp = tid >> 5;                  // unit block 0..7
    const int lane = tid & 31;
    const int g    = lane >> 2;                 // fragment group row
    const int tg   = lane & 3;                  // thread-in-group
    const int u    = warp * 8 + g;              // hidden unit owned by thread
    const int row0 = blockIdx.x * NROW;

    // ---- W fragments, tiles X={i,f} and Y={g,o} for units [8w, 8w+8) ----
    uint32_t wx[4][4], wy[4][4];
    {
        const float* ri = W_hh + (u)        * 64;
        const float* rf = W_hh + (64 + u)   * 64;
        const float* rg = W_hh + (128 + u)  * 64;
        const float* ro = W_hh + (192 + u)  * 64;
        #pragma unroll
        for (int kt = 0; kt < 4; kt++) {
            const int k0 = kt * 16 + 2 * tg;
            wx[kt][0] = pack_h2(ri[k0],     ri[k0 + 1]);
            wx[kt][1] = pack_h2(rf[k0],     rf[k0 + 1]);
            wx[kt][2] = pack_h2(ri[k0 + 8], ri[k0 + 9]);
            wx[kt][3] = pack_h2(rf[k0 + 8], rf[k0 + 9]);
            wy[kt][0] = pack_h2(rg[k0],     rg[k0 + 1]);
            wy[kt][1] = pack_h2(ro[k0],     ro[k0 + 1]);
            wy[kt][2] = pack_h2(rg[k0 + 8], rg[k0 + 9]);
            wy[kt][3] = pack_h2(ro[k0 + 8], ro[k0 + 9]);
        }
    }

    // per-unit x-path constants for gates i,f,g,o of unit u
    float wA[4], wB[4], bb_[4];
    #pragma unroll
    for (int q2 = 0; q2 < 4; q2++) {
        int j = q2 * 64 + u;
        wA[q2]  = W_ih[j * 2 + 0];
        wB[q2]  = W_ih[j * 2 + 1];
        bb_[q2] = b_ih[j] + b_hh[j];
    }

    float c[4]  = {0.f, 0.f, 0.f, 0.f};        // c-state: [nt*2 + colparity]
    float hv[4] = {0.f, 0.f, 0.f, 0.f};        // last h (for fc head)

    // h0 = 0 (both buffers)
    for (int i = tid; i < 2 * NROW * HB_PAD / 2; i += NTH)
        ((uint32_t*)hb)[i] = 0u;
    __syncthreads();

    for (int t = 0; t < T_LEN; t++) {
        const int tc = t % CH;
        if (tc == 0) {
            for (int idx = tid; idx < NROW * CH; idx += NTH) {
                int b = idx / CH, cc = idx - b * CH;
                xs[b][cc] = *(const float2*)(x + ((row0 + b) * T_LEN + t + cc) * 2);
            }
            __syncthreads();
        }

        const int p = t & 1;                    // read h buffer
        const int q = p ^ 1;                    // write h buffer

        #pragma unroll
        for (int nt = 0; nt < 2; nt++) {
            const int bb = nt * 8;              // batch base of this n-tile
            const __half* hh = hb[p][bb + g];
            uint32_t bhf[4][2];
            #pragma unroll
            for (int kt = 0; kt < 4; kt++) {
                const int k0 = kt * 16 + 2 * tg;
                bhf[kt][0] = *(const uint32_t*)(hh + k0);
                bhf[kt][1] = *(const uint32_t*)(hh + k0 + 8);
            }
            // x-gate injection: initial value of the accumulators
            const int b0 = bb + 2 * tg;
            float2 x0 = xs[b0][tc], x1 = xs[b0 + 1][tc];
            float dx[4], dy[4];
            dx[0] = fmaf(x0.y, wB[0], fmaf(x0.x, wA[0], bb_[0]));  // gi @ b0
            dx[1] = fmaf(x1.y, wB[0], fmaf(x1.x, wA[0], bb_[0]));  // gi @ b0+1
            dx[2] = fmaf(x0.y, wB[1], fmaf(x0.x, wA[1], bb_[1]));  // gf @ b0
            dx[3] = fmaf(x1.y, wB[1], fmaf(x1.x, wA[1], bb_[1]));  // gf @ b0+1
            dy[0] = fmaf(x0.y, wB[2], fmaf(x0.x, wA[2], bb_[2]));  // gg @ b0
            dy[1] = fmaf(x1.y, wB[2], fmaf(x1.x, wA[2], bb_[2]));  // gg @ b0+1
            dy[2] = fmaf(x0.y, wB[3], fmaf(x0.x, wA[3], bb_[3]));  // go @ b0
            dy[3] = fmaf(x1.y, wB[3], fmaf(x1.x, wA[3], bb_[3]));  // go @ b0+1
            // 2 independent MMA chains (X and Y), single term each
            #pragma unroll
            for (int kt = 0; kt < 4; kt++) {
                mma_f16(dx, wx[kt], bhf[kt][0], bhf[kt][1]);
                mma_f16(dy, wy[kt], bhf[kt][0], bhf[kt][1]);
            }
            // ---- activation, fully in-register (2 batch cols) ----
            #pragma unroll
            for (int e = 0; e < 2; e++) {
                const int bcol = b0 + e;
                float iv = sigmoid_f(dx[0 + e]);
                float fv = sigmoid_f(dx[2 + e]);
                float gv = tanh_f(dy[0 + e]);
                float ov = sigmoid_f(dy[2 + e]);
                const int ci = nt * 2 + e;
                float cv = fmaf(fv, c[ci], iv * gv);
                c[ci] = cv;
                float h = ov * tanh_f(cv);
                hv[ci] = h;
                hb[q][bcol][u] = __float2half_rn(h);
            }
        }
        __syncthreads();                        // h(t) published
    }

    // ---- fc head ----
    #pragma unroll
    for (int nt = 0; nt < 2; nt++) {
        const int b0 = nt * 8 + 2 * tg;
        hf[b0][u]     = hv[nt * 2 + 0];
        hf[b0 + 1][u] = hv[nt * 2 + 1];
    }
    __syncthreads();
    if (tid < NROW) {
        float s = b_fc[0];
        #pragma unroll
        for (int k = 0; k < 64; k++)
            s = fmaf(hf[tid][k], W_fc[k], s);
        out[row0 + tid] = s;
    }
}

extern "C" void kernel_launch(void* const* d_in, const int* in_sizes, int n_in,
                              void* d_out, int out_size) {
    const float* x    = (const float*)d_in[0];
    const float* W_ih = (const float*)d_in[1];
    const float* W_hh = (const float*)d_in[2];
    const float* b_ih = (const float*)d_in[3];
    const float* b_hh = (const float*)d_in[4];
    const float* W_fc = (const float*)d_in[5];
    const float* b_fc = (const float*)d_in[6];
    float* out = (float*)d_out;
    (void)in_sizes; (void)n_in; (void)out_size;

    lstm_mma<<<GRID, NTH>>>(x, W_ih, W_hh, b_ih, b_hh, W_fc, b_fc, out);
}